// round 6
// baseline (speedup 1.0000x reference)
#include <cuda_runtime.h>
#include <cstdint>

#define B_ 4
#define T_ 4096
#define C_ 1024
#define H_ 64

#define NCHUNK 4
#define CHUNK_TILES 16
#define NQT 32          // 128-query tiles

// Q: tf32 bits, pre-scaled, row-major [b][t][h]
__device__ uint32_t g_qf[B_*T_*H_];
// K, V^T: tf32 bits in mma-B-fragment swizzled layout, per 64-key tile:
//   word = q*8+g + 32*nn + 256*hi + 512*kk   (4096 words / tile)
__device__ uint32_t g_kf[B_*64*4096];
__device__ uint32_t g_vf[B_*64*4096];
__device__ uint32_t g_wt[3*64*1024];

__device__ float g_po[B_*NCHUNK*NQT*128*H_];
__device__ float g_pm[B_*NCHUNK*NQT*128];
__device__ float g_pl[B_*NCHUNK*NQT*128];

__device__ __forceinline__ uint32_t f2tf32(float x) {
    uint32_t r;
    asm("cvt.rna.tf32.f32 %0, %1;" : "=r"(r) : "f"(x));
    return r;
}

__device__ __forceinline__ void mma_tf32(float c[4], const uint32_t a[4],
                                         uint32_t b0, uint32_t b1) {
    asm volatile(
        "mma.sync.aligned.m16n8k8.row.col.f32.tf32.tf32.f32 "
        "{%0,%1,%2,%3}, {%4,%5,%6,%7}, {%8,%9}, {%0,%1,%2,%3};"
        : "+f"(c[0]), "+f"(c[1]), "+f"(c[2]), "+f"(c[3])
        : "r"(a[0]), "r"(a[1]), "r"(a[2]), "r"(a[3]), "r"(b0), "r"(b1));
}

__device__ __forceinline__ void cp16(uint32_t dst, const void* src) {
    asm volatile("cp.async.cg.shared.global [%0], [%1], 16;" :: "r"(dst), "l"(src));
}

__device__ __forceinline__ void store_bswz(uint32_t* base, int j, int d, float val) {
    int nn = j >> 3, gg = j & 7;
    int kk = d >> 3, hi = (d >> 2) & 1, qq = d & 3;
    base[(qq*8 + gg) + 32*nn + 256*hi + 512*kk] = f2tf32(val);
}

// ---------------------------------------------------------------------------
// Kernel 0: convert W -> tf32, transposed [n][k]
// ---------------------------------------------------------------------------
__global__ __launch_bounds__(256) void wconv_kernel(
    const float* __restrict__ Wk, const float* __restrict__ Wq,
    const float* __restrict__ Wv)
{
    int idx = blockIdx.x * 256 + threadIdx.x;
    int wi = idx >> 16;
    int r  = idx & 65535;
    int k  = r >> 6;
    int n  = r & 63;
    const float* W = (wi == 0) ? Wk : ((wi == 1) ? Wq : Wv);
    g_wt[((size_t)wi*64 + n)*1024 + k] = f2tf32(W[k*64 + n]);
}

// ---------------------------------------------------------------------------
// Kernel 1: fused QKV (unchanged from R5)
// ---------------------------------------------------------------------------
#define XST 36
#define WST 36
#define XBUF (64*XST)
#define WBUF (192*WST)

__global__ __launch_bounds__(128) void qkv_kernel(const float* __restrict__ x)
{
    extern __shared__ float smf[];
    float*    Xs = smf;
    uint32_t* Ws = (uint32_t*)(smf + 2*XBUF);

    const int row0 = blockIdx.x * 64;
    const int tid  = threadIdx.x;
    const int w    = tid >> 5;
    const int lane = tid & 31;
    const int g    = lane >> 2;
    const int q    = lane & 3;

    float acc[4][6][4] = {};

    {
        #pragma unroll
        for (int j = 0; j < 4; j++) {
            int idx = tid + 128*j;
            int r = idx >> 3, c4 = (idx & 7) * 4;
            cp16((uint32_t)__cvta_generic_to_shared(&Xs[r*XST + c4]),
                 &x[(size_t)(row0 + r)*C_ + c4]);
        }
        #pragma unroll
        for (int j = 0; j < 12; j++) {
            int idx = tid + 128*j;
            int r = idx >> 3, c4 = (idx & 7) * 4;
            cp16((uint32_t)__cvta_generic_to_shared(&Ws[r*WST + c4]),
                 &g_wt[(size_t)r*1024 + c4]);
        }
        asm volatile("cp.async.commit_group;");
    }

    for (int ch = 0; ch < 32; ch++) {
        const int p = ch & 1;
        if (ch + 1 < 32) {
            const int k0 = (ch + 1) * 32;
            const int pn = p ^ 1;
            #pragma unroll
            for (int j = 0; j < 4; j++) {
                int idx = tid + 128*j;
                int r = idx >> 3, c4 = (idx & 7) * 4;
                cp16((uint32_t)__cvta_generic_to_shared(&Xs[pn*XBUF + r*XST + c4]),
                     &x[(size_t)(row0 + r)*C_ + k0 + c4]);
            }
            #pragma unroll
            for (int j = 0; j < 12; j++) {
                int idx = tid + 128*j;
                int r = idx >> 3, c4 = (idx & 7) * 4;
                cp16((uint32_t)__cvta_generic_to_shared(&Ws[pn*WBUF + r*WST + c4]),
                     &g_wt[(size_t)r*1024 + k0 + c4]);
            }
            asm volatile("cp.async.commit_group;");
            asm volatile("cp.async.wait_group 1;");
        } else {
            asm volatile("cp.async.wait_group 0;");
        }
        __syncthreads();

        const float*    Xc = Xs + p*XBUF;
        const uint32_t* Wc = Ws + p*WBUF;

        #pragma unroll
        for (int ks = 0; ks < 4; ks++) {
            uint32_t a[4][4];
            #pragma unroll
            for (int m = 0; m < 4; m++) {
                int row = m*16 + g;
                a[m][0] = f2tf32(Xc[row*XST + ks*8 + q]);
                a[m][1] = f2tf32(Xc[(row + 8)*XST + ks*8 + q]);
                a[m][2] = f2tf32(Xc[row*XST + ks*8 + q + 4]);
                a[m][3] = f2tf32(Xc[(row + 8)*XST + ks*8 + q + 4]);
            }
            #pragma unroll
            for (int j = 0; j < 6; j++) {
                int rn = w*48 + j*8 + g;
                uint32_t b0 = Wc[rn*WST + ks*8 + q];
                uint32_t b1 = Wc[rn*WST + ks*8 + q + 4];
                #pragma unroll
                for (int m = 0; m < 4; m++)
                    mma_tf32(acc[m][j], a[m], b0, b1);
            }
        }
        __syncthreads();
    }

    const float scale = 0.03125f;
    #pragma unroll
    for (int m = 0; m < 4; m++) {
        #pragma unroll
        for (int j = 0; j < 6; j++) {
            int gcol = w*48 + j*8 + q*2;
            int sel  = gcol >> 6;
            int col  = gcol & 63;
            int row  = row0 + m*16 + g;
            int bb = row >> 12, t = row & 4095;
            int kt = t >> 6, jj = t & 63;
            if (sel == 0) {
                uint32_t* base = g_kf + (((size_t)bb*64 + kt) << 12);
                store_bswz(base, jj,     col,     acc[m][j][0]);
                store_bswz(base, jj,     col + 1, acc[m][j][1]);
                store_bswz(base, jj + 8, col,     acc[m][j][2]);
                store_bswz(base, jj + 8, col + 1, acc[m][j][3]);
            } else if (sel == 1) {
                g_qf[(size_t)row*H_ + col]       = f2tf32(acc[m][j][0] * scale);
                g_qf[(size_t)row*H_ + col + 1]   = f2tf32(acc[m][j][1] * scale);
                g_qf[(size_t)(row+8)*H_ + col]   = f2tf32(acc[m][j][2] * scale);
                g_qf[(size_t)(row+8)*H_ + col+1] = f2tf32(acc[m][j][3] * scale);
            } else {
                uint32_t* base = g_vf + (((size_t)bb*64 + kt) << 12);
                store_bswz(base, col,     jj,     acc[m][j][0]);
                store_bswz(base, col + 1, jj,     acc[m][j][1]);
                store_bswz(base, col,     jj + 8, acc[m][j][2]);
                store_bswz(base, col + 1, jj + 8, acc[m][j][3]);
            }
        }
    }
}

// ---------------------------------------------------------------------------
// Kernel 2: flash attention partial pass. 128-query CTA, 8 warps.
// K/V tiles (64 keys) shared by all warps; cp.async double-buffered.
// ---------------------------------------------------------------------------
#define SS 68
#define TILE_W 4096

__global__ __launch_bounds__(256, 2) void attn_part_kernel()
{
    extern __shared__ uint32_t sm[];
    uint32_t* Kf = sm;                       // [2][4096]
    uint32_t* Vf = sm + 2*TILE_W;            // [2][4096]
    uint32_t* Ps = sm + 4*TILE_W;            // [128][SS]

    const int qt = blockIdx.x;               // 128-query tile
    const int c  = blockIdx.y;
    const int b  = blockIdx.z;

    const int kb_last = 2*qt + 1;            // last valid 64-key tile
    const int kb_lo = c * CHUNK_TILES;
    if (kb_lo > kb_last) return;
    const int kb_hi = min(kb_last, kb_lo + CHUNK_TILES - 1);

    const int tid = threadIdx.x;
    const int w   = tid >> 5;
    const int lane = tid & 31;
    const int g   = lane >> 2;
    const int q   = lane & 3;
    const int bgq = q*8 + g;

    // stage Q (pre-scaled tf32): 128 rows
    const uint32_t* qg = g_qf + ((size_t)b * T_ + (size_t)qt * 128) * H_;
    for (int i = tid * 4; i < 128 * 64; i += 1024) {
        int r = i >> 6, cc = i & 63;
        *reinterpret_cast<uint4*>(&Ps[r * SS + cc]) =
            *reinterpret_cast<const uint4*>(&qg[r * 64 + cc]);
    }

    const uint32_t* ktile = g_kf + (((size_t)b*64 + kb_lo) << 12);
    const uint32_t* vtile = g_vf + (((size_t)b*64 + kb_lo) << 12);

    #pragma unroll
    for (int j = 0; j < 4; j++) {
        int off = (tid + 256*j) * 4;
        cp16((uint32_t)__cvta_generic_to_shared(&Kf[off]), ktile + off);
        cp16((uint32_t)__cvta_generic_to_shared(&Vf[off]), vtile + off);
    }
    asm volatile("cp.async.commit_group;");

    __syncthreads();

    uint32_t qa[8][4];
    #pragma unroll
    for (int kk = 0; kk < 8; kk++) {
        int row = w * 16 + g;
        qa[kk][0] = Ps[row * SS + kk * 8 + q];
        qa[kk][1] = Ps[(row + 8) * SS + kk * 8 + q];
        qa[kk][2] = Ps[row * SS + kk * 8 + q + 4];
        qa[kk][3] = Ps[(row + 8) * SS + kk * 8 + q + 4];
    }

    float o[8][4] = {};
    float m0 = -1e30f, m1 = -1e30f, l0 = 0.0f, l1 = 0.0f;

    for (int kb = kb_lo; kb <= kb_hi; kb++) {
        const int p = (kb - kb_lo) & 1;
        if (kb < kb_hi) {
            const int pn = p ^ 1;
            const uint32_t* kt2 = g_kf + (((size_t)b*64 + kb + 1) << 12);
            const uint32_t* vt2 = g_vf + (((size_t)b*64 + kb + 1) << 12);
            #pragma unroll
            for (int j = 0; j < 4; j++) {
                int off = (tid + 256*j) * 4;
                cp16((uint32_t)__cvta_generic_to_shared(&Kf[pn*TILE_W + off]), kt2 + off);
                cp16((uint32_t)__cvta_generic_to_shared(&Vf[pn*TILE_W + off]), vt2 + off);
            }
            asm volatile("cp.async.commit_group;");
            asm volatile("cp.async.wait_group 1;");
        } else {
            asm volatile("cp.async.wait_group 0;");
        }
        __syncthreads();

        const uint32_t* Kc = Kf + p*TILE_W + bgq;
        const uint32_t* Vc = Vf + p*TILE_W + bgq;

        // S = Q @ K^T
        float s[8][4] = {};
        #pragma unroll
        for (int kk = 0; kk < 8; kk++) {
            #pragma unroll
            for (int n = 0; n < 8; n++) {
                uint32_t b0 = Kc[512*kk + 32*n];
                uint32_t b1 = Kc[512*kk + 32*n + 256];
                mma_tf32(s[n], qa[kk], b0, b1);
            }
        }

        // causal mask on the two diagonal-crossing k-tiles
        if (kb >= 2*qt) {
            int grow = qt*128 + w*16 + g;
            #pragma unroll
            for (int n = 0; n < 8; n++) {
                int gc = kb*64 + n*8 + q*2;
                if (gc     > grow)     s[n][0] = -1e30f;
                if (gc + 1 > grow)     s[n][1] = -1e30f;
                if (gc     > grow + 8) s[n][2] = -1e30f;
                if (gc + 1 > grow + 8) s[n][3] = -1e30f;
            }
        }

        float tmax0 = -1e30f, tmax1 = -1e30f;
        #pragma unroll
        for (int n = 0; n < 8; n++) {
            tmax0 = fmaxf(tmax0, fmaxf(s[n][0], s[n][1]));
            tmax1 = fmaxf(tmax1, fmaxf(s[n][2], s[n][3]));
        }
        tmax0 = fmaxf(tmax0, __shfl_xor_sync(0xffffffff, tmax0, 1));
        tmax0 = fmaxf(tmax0, __shfl_xor_sync(0xffffffff, tmax0, 2));
        tmax1 = fmaxf(tmax1, __shfl_xor_sync(0xffffffff, tmax1, 1));
        tmax1 = fmaxf(tmax1, __shfl_xor_sync(0xffffffff, tmax1, 2));

        float m0n = fmaxf(m0, tmax0);
        float m1n = fmaxf(m1, tmax1);
        float al0 = __expf(m0 - m0n);
        float al1 = __expf(m1 - m1n);

        float sum0 = 0.0f, sum1 = 0.0f;
        #pragma unroll
        for (int n = 0; n < 8; n++) {
            s[n][0] = __expf(s[n][0] - m0n);
            s[n][1] = __expf(s[n][1] - m0n);
            s[n][2] = __expf(s[n][2] - m1n);
            s[n][3] = __expf(s[n][3] - m1n);
            sum0 += s[n][0] + s[n][1];
            sum1 += s[n][2] + s[n][3];
        }
        sum0 += __shfl_xor_sync(0xffffffff, sum0, 1);
        sum0 += __shfl_xor_sync(0xffffffff, sum0, 2);
        sum1 += __shfl_xor_sync(0xffffffff, sum1, 1);
        sum1 += __shfl_xor_sync(0xffffffff, sum1, 2);

        l0 = l0 * al0 + sum0;  m0 = m0n;
        l1 = l1 * al1 + sum1;  m1 = m1n;

        #pragma unroll
        for (int n = 0; n < 8; n++) {
            o[n][0] *= al0; o[n][1] *= al0;
            o[n][2] *= al1; o[n][3] *= al1;
        }

        // P -> A-layout via per-warp smem roundtrip
        {
            int row = w * 16 + g;
            #pragma unroll
            for (int n = 0; n < 8; n++) {
                int col = n * 8 + q * 2;
                *reinterpret_cast<uint2*>(&Ps[row * SS + col]) =
                    make_uint2(f2tf32(s[n][0]), f2tf32(s[n][1]));
                *reinterpret_cast<uint2*>(&Ps[(row + 8) * SS + col]) =
                    make_uint2(f2tf32(s[n][2]), f2tf32(s[n][3]));
            }
        }
        __syncwarp();

        // O += P @ V
        #pragma unroll
        for (int kk = 0; kk < 8; kk++) {
            int row = w * 16 + g;
            uint32_t pa[4];
            pa[0] = Ps[row * SS + kk * 8 + q];
            pa[1] = Ps[(row + 8) * SS + kk * 8 + q];
            pa[2] = Ps[row * SS + kk * 8 + q + 4];
            pa[3] = Ps[(row + 8) * SS + kk * 8 + q + 4];
            #pragma unroll
            for (int n = 0; n < 8; n++) {
                uint32_t b0 = Vc[512*kk + 32*n];
                uint32_t b1 = Vc[512*kk + 32*n + 256];
                mma_tf32(o[n], pa, b0, b1);
            }
        }
        __syncthreads();
    }

    const size_t pbase = ((size_t)(b * NCHUNK + c) * NQT + qt);
    float* po = g_po + pbase * 128 * H_;
    float* pm = g_pm + pbase * 128;
    float* pl = g_pl + pbase * 128;

    const int r0 = w * 16 + g;
    #pragma unroll
    for (int n = 0; n < 8; n++) {
        int col = n * 8 + q * 2;
        *reinterpret_cast<float2*>(&po[r0 * H_ + col]) = make_float2(o[n][0], o[n][1]);
        *reinterpret_cast<float2*>(&po[(r0 + 8) * H_ + col]) = make_float2(o[n][2], o[n][3]);
    }
    if (q == 0) {
        pm[r0] = m0; pl[r0] = l0;
        pm[r0 + 8] = m1; pl[r0 + 8] = l1;
    }
}

// ---------------------------------------------------------------------------
// Kernel 3: merge split-K partials. grid (32 qt, B), block 512.
// ---------------------------------------------------------------------------
__global__ __launch_bounds__(512) void attn_merge_kernel(float* __restrict__ out)
{
    const int qt = blockIdx.x;
    const int b  = blockIdx.y;
    const int t  = threadIdx.x;
    const int row = t >> 2;          // 0..127
    const int c0  = (t & 3) * 16;

    const int nc = (2*qt + 1) / CHUNK_TILES + 1;

    float m[NCHUNK], l[NCHUNK];
    float M = -1e30f;
    #pragma unroll
    for (int c = 0; c < NCHUNK; c++) {
        if (c < nc) {
            size_t pbase = ((size_t)(b * NCHUNK + c) * NQT + qt);
            m[c] = g_pm[pbase * 128 + row];
            l[c] = g_pl[pbase * 128 + row];
            M = fmaxf(M, m[c]);
        }
    }
    float L = 0.0f, sc[NCHUNK];
    #pragma unroll
    for (int c = 0; c < NCHUNK; c++) {
        if (c < nc) {
            sc[c] = __expf(m[c] - M);
            L += l[c] * sc[c];
        }
    }
    const float invL = 1.0f / L;

    float* og = out + ((size_t)b * T_ + (size_t)qt * 128 + row) * H_ + c0;

    #pragma unroll
    for (int j = 0; j < 16; j += 4) {
        float4 acc = make_float4(0.f, 0.f, 0.f, 0.f);
        #pragma unroll
        for (int c = 0; c < NCHUNK; c++) {
            if (c < nc) {
                size_t pbase = ((size_t)(b * NCHUNK + c) * NQT + qt);
                const float* po = g_po + (pbase * 128 + row) * H_ + c0 + j;
                float4 v4 = *reinterpret_cast<const float4*>(po);
                acc.x += v4.x * sc[c]; acc.y += v4.y * sc[c];
                acc.z += v4.z * sc[c]; acc.w += v4.w * sc[c];
            }
        }
        acc.x *= invL; acc.y *= invL; acc.z *= invL; acc.w *= invL;
        *reinterpret_cast<float4*>(&og[j]) = acc;
    }
}

// ---------------------------------------------------------------------------
extern "C" void kernel_launch(void* const* d_in, const int* in_sizes, int n_in,
                              void* d_out, int out_size)
{
    const float* x  = (const float*)d_in[0];
    const float* Wk = (const float*)d_in[1];
    const float* Wq = (const float*)d_in[2];
    const float* Wv = (const float*)d_in[3];
    float* out = (float*)d_out;

    wconv_kernel<<<768, 256>>>(Wk, Wq, Wv);

    const int qkv_smem = (2*XBUF + 2*WBUF) * (int)sizeof(float);
    cudaFuncSetAttribute(qkv_kernel,
                         cudaFuncAttributeMaxDynamicSharedMemorySize, qkv_smem);
    qkv_kernel<<<(B_*T_)/64, 128, qkv_smem>>>(x);

    const int attn_smem = (4*TILE_W + 128*SS) * (int)sizeof(uint32_t);
    cudaFuncSetAttribute(attn_part_kernel,
                         cudaFuncAttributeMaxDynamicSharedMemorySize, attn_smem);
    attn_part_kernel<<<dim3(NQT, NCHUNK, B_), 256, attn_smem>>>();

    attn_merge_kernel<<<dim3(NQT, B_), 512>>>(out);
}